// round 8
// baseline (speedup 1.0000x reference)
#include <cuda_runtime.h>
#include <cuda_bf16.h>
#include <cstdint>

// Problem constants (fixed by the reference)
constexpr int N  = 100000;   // nodes
constexpr int F  = 1433;     // input features
constexpr int H  = 67;       // hidden
constexpr int C  = 7;        // classes
constexpr int E  = 3200000;  // edges

// ---------------- scratch (no allocations allowed) ----------------
__device__ float g_h1s[N * H];   // (x@W1) * dinv[row]
__device__ float g_a1 [N * H];   // post-aggregate, +b1, leaky_relu
__device__ float g_h2s[N * C];   // (a1@W2) * dinv[row]
__device__ float g_dinv[N];
__device__ int   g_cnt[N];
__device__ int   g_start[N];
__device__ int   g_cursor[N];
__device__ int   g_rows[E];
__device__ int   g_bsums[128];

// ---------------- packed f32x2 helpers ----------------
__device__ __forceinline__ unsigned long long pk2(float lo, float hi) {
    unsigned long long r;
    asm("mov.b64 %0, {%1, %2};" : "=l"(r) : "f"(lo), "f"(hi));
    return r;
}
__device__ __forceinline__ void unpk2(unsigned long long v, float &lo, float &hi) {
    asm("mov.b64 {%0, %1}, %2;" : "=f"(lo), "=f"(hi) : "l"(v));
}
__device__ __forceinline__ void fma2(unsigned long long &d, unsigned long long a, unsigned long long b) {
    asm("fma.rn.f32x2 %0, %1, %2, %0;" : "+l"(d) : "l"(a), "l"(b));
}

// ---------------- degree / CSR construction ----------------
__global__ void zero_cnt_kernel() {
    int i = blockIdx.x * blockDim.x + threadIdx.x;
    if (i < N) g_cnt[i] = 0;
}

__global__ void hist_kernel(const int* __restrict__ col) {
    int e = blockIdx.x * blockDim.x + threadIdx.x;
    if (e < E) atomicAdd(&g_cnt[col[e]], 1);
}

__global__ __launch_bounds__(1024) void scan1_kernel() {
    __shared__ int s[1024];
    int i = blockIdx.x * 1024 + threadIdx.x;
    int v = (i < N) ? g_cnt[i] : 0;
    s[threadIdx.x] = v;
    __syncthreads();
    #pragma unroll
    for (int off = 1; off < 1024; off <<= 1) {
        int t = 0;
        if ((int)threadIdx.x >= off) t = s[threadIdx.x - off];
        __syncthreads();
        s[threadIdx.x] += t;
        __syncthreads();
    }
    if (i < N) g_start[i] = s[threadIdx.x] - v;   // exclusive
    if (threadIdx.x == 1023) g_bsums[blockIdx.x] = s[1023];
}

__global__ void scan2_kernel(int nblocks) {
    __shared__ int s[128];
    if ((int)threadIdx.x < nblocks) s[threadIdx.x] = g_bsums[threadIdx.x];
    __syncthreads();
    if (threadIdx.x == 0) {
        int run = 0;
        for (int b = 0; b < nblocks; b++) { int t = s[b]; s[b] = run; run += t; }
    }
    __syncthreads();
    if ((int)threadIdx.x < nblocks) g_bsums[threadIdx.x] = s[threadIdx.x];
}

__global__ void scan3_kernel() {
    int i = blockIdx.x * blockDim.x + threadIdx.x;
    if (i < N) {
        int st = g_start[i] + g_bsums[i >> 10];
        g_start[i]  = st;
        g_cursor[i] = st;
        g_dinv[i]   = rsqrtf((float)(g_cnt[i] + 1));  // +1 for self loop
    }
}

__global__ void fill_kernel(const int* __restrict__ row, const int* __restrict__ col) {
    int e = blockIdx.x * blockDim.x + threadIdx.x;
    if (e < E) {
        int c = col[e];
        int p = atomicAdd(&g_cursor[c], 1);
        g_rows[p] = row[e];
    }
}

// ---------------- GEMM1: h1s = (x @ W1) * dinv ----------------
// BM=128 rows, all 67 cols per block, BK=16. 256 threads = 16 (col) x 16 (row groups).
// Each thread: 8 rows x 5 cols, accumulated as packed f32x2 row pairs.
__global__ __launch_bounds__(256) void gemm1_kernel(const float* __restrict__ x,
                                                    const float* __restrict__ W1) {
    __shared__ float As[128][17];   // [row][k], pad 17
    __shared__ float Bs[16][68];    // [k][col], col 67 zeroed

    int tid = threadIdx.x;
    int ry = tid >> 4, cx = tid & 15;
    int rowBase = blockIdx.x * 128;
    int r0 = ry * 8;

    int jc[5];
    #pragma unroll
    for (int t = 0; t < 5; t++) { int j = cx + 16 * t; jc[t] = (j < H) ? j : H; }

    unsigned long long acc[4][5];
    #pragma unroll
    for (int p = 0; p < 4; p++)
        #pragma unroll
        for (int t = 0; t < 5; t++) acc[p][t] = 0ULL;

    for (int kk = 0; kk < F; kk += 16) {
        // load A tile (coalesced along k, 16 floats per row)
        #pragma unroll
        for (int i = 0; i < 8; i++) {
            int idx = tid + i * 256;
            int r = idx >> 4, k = idx & 15;
            int grow = rowBase + r, gk = kk + k;
            float v = 0.f;
            if (grow < N && gk < F) v = x[grow * F + gk];
            As[r][k] = v;
        }
        // load B tile (16 x 68, col 67 = 0)
        #pragma unroll
        for (int i = 0; i < 5; i++) {
            int idx = tid + i * 256;
            if (idx < 16 * 68) {
                int k = idx / 68, j = idx - k * 68;
                int gk = kk + k;
                float v = 0.f;
                if (j < H && gk < F) v = W1[gk * H + j];
                Bs[k][j] = v;
            }
        }
        __syncthreads();

        #pragma unroll
        for (int k = 0; k < 16; k++) {
            float a[8];
            #pragma unroll
            for (int i = 0; i < 8; i++) a[i] = As[r0 + i][k];
            unsigned long long ap[4];
            #pragma unroll
            for (int p = 0; p < 4; p++) ap[p] = pk2(a[2 * p], a[2 * p + 1]);
            #pragma unroll
            for (int t = 0; t < 5; t++) {
                float b = Bs[k][jc[t]];
                unsigned long long bb = pk2(b, b);
                #pragma unroll
                for (int p = 0; p < 4; p++) fma2(acc[p][t], ap[p], bb);
            }
        }
        __syncthreads();
    }

    // epilogue: scale by dinv[row], store
    #pragma unroll
    for (int p = 0; p < 4; p++) {
        #pragma unroll
        for (int t = 0; t < 5; t++) {
            int col = cx + 16 * t;
            if (col >= H) continue;
            float lo, hi;
            unpk2(acc[p][t], lo, hi);
            int r = rowBase + r0 + 2 * p;
            if (r < N)     g_h1s[r * H + col]       = lo * g_dinv[r];
            if (r + 1 < N) g_h1s[(r + 1) * H + col] = hi * g_dinv[r + 1];
        }
    }
}

// ---------------- aggregate layer 1 (+b1, leaky_relu) ----------------
// one warp per node; lane handles features {lane, lane+32, lane+64(<3)}
__global__ __launch_bounds__(256) void agg1_kernel(const float* __restrict__ b1) {
    int warp = (blockIdx.x * 256 + threadIdx.x) >> 5;
    if (warp >= N) return;
    int lane = threadIdx.x & 31;

    const float* hs = g_h1s + warp * H;
    float s0 = hs[lane];
    float s1 = hs[lane + 32];
    float s2 = (lane < 3) ? hs[lane + 64] : 0.f;

    int sbeg = g_start[warp], n = g_cnt[warp];
    const int* rp = g_rows + sbeg;
    for (int k = 0; k < n; k++) {
        int r = rp[k];
        const float* hr = g_h1s + r * H;
        s0 += hr[lane];
        s1 += hr[lane + 32];
        if (lane < 3) s2 += hr[lane + 64];
    }
    float dv = g_dinv[warp];
    float* out = g_a1 + warp * H;
    float v;
    v = fmaf(dv, s0, b1[lane]);      out[lane]      = (v > 0.f) ? v : 0.01f * v;
    v = fmaf(dv, s1, b1[lane + 32]); out[lane + 32] = (v > 0.f) ? v : 0.01f * v;
    if (lane < 3) {
        v = fmaf(dv, s2, b1[lane + 64]); out[lane + 64] = (v > 0.f) ? v : 0.01f * v;
    }
}

// ---------------- GEMM2: h2s = (a1 @ W2) * dinv ----------------
__global__ __launch_bounds__(128) void gemm2_kernel(const float* __restrict__ W2) {
    __shared__ float as[128 * H];
    __shared__ float w[H * C];
    int tid = threadIdx.x;
    int base = blockIdx.x * 128;
    int nn = N - base; if (nn > 128) nn = 128;
    int total = nn * H;
    for (int i = tid; i < total; i += 128) as[i] = g_a1[base * H + i];
    for (int i = tid; i < H * C; i += 128) w[i] = W2[i];
    __syncthreads();
    if (tid < nn) {
        float acc[C];
        #pragma unroll
        for (int j = 0; j < C; j++) acc[j] = 0.f;
        const float* ar = as + tid * H;
        #pragma unroll 4
        for (int k = 0; k < H; k++) {
            float av = ar[k];
            #pragma unroll
            for (int j = 0; j < C; j++) acc[j] = fmaf(av, w[k * C + j], acc[j]);
        }
        int node = base + tid;
        float dv = g_dinv[node];
        #pragma unroll
        for (int j = 0; j < C; j++) g_h2s[node * C + j] = acc[j] * dv;
    }
}

// ---------------- aggregate layer 2 + b2 + log_softmax ----------------
// 8 lanes per node (4 nodes per warp); N % 32 == 0 so every lane group is valid.
__global__ __launch_bounds__(256) void agg2_kernel(const float* __restrict__ b2,
                                                   float* __restrict__ out) {
    int warp = (blockIdx.x * 256 + threadIdx.x) >> 5;
    int lane = threadIdx.x & 31;
    int g = lane >> 3, j = lane & 7;
    int n = warp * 4 + g;   // < N by construction (3125 blocks)

    float acc = (j < C) ? g_h2s[n * C + j] : 0.f;
    int sbeg = g_start[n], c = g_cnt[n];
    const int* rp = g_rows + sbeg;
    for (int k = 0; k < c; k++) {
        int r = rp[k];
        if (j < C) acc += g_h2s[r * C + j];
    }
    float logit = (j < C) ? fmaf(g_dinv[n], acc, b2[j]) : -3.0e38f;

    float m = logit;
    #pragma unroll
    for (int o = 4; o > 0; o >>= 1)
        m = fmaxf(m, __shfl_xor_sync(0xffffffffu, m, o, 8));
    float ex = (j < C) ? expf(logit - m) : 0.f;
    float sum = ex;
    #pragma unroll
    for (int o = 4; o > 0; o >>= 1)
        sum += __shfl_xor_sync(0xffffffffu, sum, o, 8);
    if (j < C) out[n * C + j] = logit - m - logf(sum);
}

// ---------------- launch ----------------
extern "C" void kernel_launch(void* const* d_in, const int* in_sizes, int n_in,
                              void* d_out, int out_size) {
    const float* x    = (const float*)d_in[0];
    const int*   ei   = (const int*)d_in[1];   // [2, E] row-major: first E = src, next E = dst
    const float* W1   = (const float*)d_in[2];
    const float* b1   = (const float*)d_in[3];
    const float* W2   = (const float*)d_in[4];
    const float* b2   = (const float*)d_in[5];
    float*       out  = (float*)d_out;

    const int* row = ei;
    const int* col = ei + E;

    int nB = (N + 255) / 256;
    int eB = (E + 255) / 256;
    int sB = (N + 1023) / 1024;     // 98

    zero_cnt_kernel<<<nB, 256>>>();
    hist_kernel<<<eB, 256>>>(col);
    scan1_kernel<<<sB, 1024>>>();
    scan2_kernel<<<1, 128>>>(sB);
    scan3_kernel<<<nB, 256>>>();
    fill_kernel<<<eB, 256>>>(row, col);

    gemm1_kernel<<<(N + 127) / 128, 256>>>(x, W1);
    agg1_kernel<<<(N * 32 + 255) / 256, 256>>>(b1);
    gemm2_kernel<<<(N + 127) / 128, 128>>>(W2);
    agg2_kernel<<<(N * 8 + 255) / 256, 256>>>(b2, out);
}

// round 11
// speedup vs baseline: 1.5373x; 1.5373x over previous
#include <cuda_runtime.h>
#include <cuda_bf16.h>
#include <cstdint>

// Problem constants (fixed by the reference)
constexpr int N  = 100000;   // nodes
constexpr int F  = 1433;     // input features
constexpr int H  = 67;       // hidden
constexpr int C  = 7;        // classes
constexpr int E  = 3200000;  // edges

constexpr int BN = 80;       // H padded to 80 (10 n-tiles of 8, splits 2-ways)
constexpr int FP = 1440;     // F padded to multiple of 32
constexpr int KCH = FP / 32; // 45 K-chunks of 32

// ---------------- scratch (no allocations allowed) ----------------
__device__ float g_h1s[N * H];     // (x@W1) * dinv[row]
__device__ float g_a1 [N * H];     // post-aggregate, +b1, leaky_relu
__device__ float g_h2s[N * C];     // (a1@W2) * dinv[row]
__device__ float g_dinv[N];
__device__ int   g_cnt[N];
__device__ int   g_start[N];
__device__ int   g_cursor[N];
__device__ int   g_rows[E];
__device__ int   g_bsums[128];
__device__ float g_w1bh[BN * FP];  // W1^T hi (tf32-rounded), k-major, zero padded
__device__ float g_w1bl[BN * FP];  // W1^T lo residual

// ---------------- helpers ----------------
__device__ __forceinline__ uint32_t smem_to_u32(const void* p) {
    uint32_t a;
    asm("{ .reg .u64 t; cvta.to.shared.u64 t, %1; cvt.u32.u64 %0, t; }"
        : "=r"(a) : "l"(p));
    return a;
}
__device__ __forceinline__ uint32_t f2tf32(float f) {
    uint32_t r; asm("cvt.rna.tf32.f32 %0, %1;" : "=r"(r) : "f"(f)); return r;
}
__device__ __forceinline__ void cp4(uint32_t dst, const void* src, uint32_t sz) {
    asm volatile("cp.async.ca.shared.global [%0], [%1], 4, %2;"
                 :: "r"(dst), "l"(src), "r"(sz) : "memory");
}
__device__ __forceinline__ void cp16(uint32_t dst, const void* src) {
    asm volatile("cp.async.cg.shared.global [%0], [%1], 16;"
                 :: "r"(dst), "l"(src) : "memory");
}
__device__ __forceinline__ void mma_tf32(float* d, const uint32_t* a, const uint32_t* b) {
    asm volatile(
        "mma.sync.aligned.m16n8k8.row.col.f32.tf32.tf32.f32 "
        "{%0,%1,%2,%3}, {%4,%5,%6,%7}, {%8,%9}, {%0,%1,%2,%3};"
        : "+f"(d[0]), "+f"(d[1]), "+f"(d[2]), "+f"(d[3])
        : "r"(a[0]), "r"(a[1]), "r"(a[2]), "r"(a[3]), "r"(b[0]), "r"(b[1]));
}

// ---------------- W1 transpose + tf32 split:  [n][k], zero padded ----------------
__global__ void w1split_kernel(const float* __restrict__ W1) {
    int i = blockIdx.x * 256 + threadIdx.x;
    if (i < BN * FP) {
        int n = i / FP, k = i - n * FP;
        float w = (n < H && k < F) ? W1[k * H + n] : 0.f;
        uint32_t hi = f2tf32(w);
        g_w1bh[i] = __uint_as_float(hi);
        g_w1bl[i] = w - __uint_as_float(hi);
    }
}

// ---------------- degree / CSR construction ----------------
__global__ void zero_cnt_kernel() {
    int i = blockIdx.x * blockDim.x + threadIdx.x;
    if (i < N) g_cnt[i] = 0;
}
__global__ void hist_kernel(const int* __restrict__ col) {
    int e = blockIdx.x * blockDim.x + threadIdx.x;
    if (e < E) atomicAdd(&g_cnt[col[e]], 1);
}
__global__ __launch_bounds__(1024) void scan1_kernel() {
    __shared__ int s[1024];
    int i = blockIdx.x * 1024 + threadIdx.x;
    int v = (i < N) ? g_cnt[i] : 0;
    s[threadIdx.x] = v;
    __syncthreads();
    #pragma unroll
    for (int off = 1; off < 1024; off <<= 1) {
        int t = 0;
        if ((int)threadIdx.x >= off) t = s[threadIdx.x - off];
        __syncthreads();
        s[threadIdx.x] += t;
        __syncthreads();
    }
    if (i < N) g_start[i] = s[threadIdx.x] - v;
    if (threadIdx.x == 1023) g_bsums[blockIdx.x] = s[1023];
}
__global__ void scan2_kernel(int nblocks) {
    __shared__ int s[128];
    if ((int)threadIdx.x < nblocks) s[threadIdx.x] = g_bsums[threadIdx.x];
    __syncthreads();
    if (threadIdx.x == 0) {
        int run = 0;
        for (int b = 0; b < nblocks; b++) { int t = s[b]; s[b] = run; run += t; }
    }
    __syncthreads();
    if ((int)threadIdx.x < nblocks) g_bsums[threadIdx.x] = s[threadIdx.x];
}
__global__ void scan3_kernel() {
    int i = blockIdx.x * blockDim.x + threadIdx.x;
    if (i < N) {
        int st = g_start[i] + g_bsums[i >> 10];
        g_start[i]  = st;
        g_cursor[i] = st;
        g_dinv[i]   = rsqrtf((float)(g_cnt[i] + 1));
    }
}
__global__ void fill_kernel(const int* __restrict__ row, const int* __restrict__ col) {
    int e = blockIdx.x * blockDim.x + threadIdx.x;
    if (e < E) {
        int c = col[e];
        int p = atomicAdd(&g_cursor[c], 1);
        g_rows[p] = row[e];
    }
}

// ---------------- GEMM1 (mma.sync tf32, 3xTF32 split): h1s = (x @ W1) * dinv ---
// CTA: 128 rows x 80 cols (67 written), K in chunks of 32, cp.async double buffer.
// 8 warps: mg = wid>>1 picks 32-row slab (2 m16 frags), ng = wid&1 picks 40 cols
// (5 n8 tiles). 30 HMMA + 28 conflict-free LDS per warp per k8-step.
// SMEM (73728 B): A0@0 A1@16384 (16KB each), Bh0@32768 Bl0@43008 Bh1@53248
// Bl1@63488 (10KB each). 16B-group XOR swizzle within 128B rows.
__global__ __launch_bounds__(256, 2) void gemm1_mma(const float* __restrict__ x) {
    extern __shared__ char smem[];
    const uint32_t sb = smem_to_u32(smem);
    const int tid = threadIdx.x;
    const int wid = tid >> 5, lane = tid & 31;
    const int gr = lane >> 2, tg = lane & 3;
    const int mg = wid >> 1, ng = wid & 1;
    const int rowBase = blockIdx.x * 128;

    const uint32_t A_OFF[2]  = {0u, 16384u};
    const uint32_t BH_OFF[2] = {32768u, 53248u};
    const uint32_t BL_OFF[2] = {43008u, 63488u};

    float acc[2][5][4];
    #pragma unroll
    for (int mt = 0; mt < 2; mt++)
        #pragma unroll
        for (int nt = 0; nt < 5; nt++)
            #pragma unroll
            for (int e = 0; e < 4; e++) acc[mt][nt][e] = 0.f;

    auto fetch = [&](int c, int buf) {
        const int kk = c * 32;
        // A tile: 128 rows x 32 floats. x rows are only 4B-aligned -> 4B cp.async.
        #pragma unroll
        for (int i = 0; i < 16; i++) {
            int q = tid + i * 256;                 // 0..4095
            int r = q >> 5, k = q & 31;
            int row = rowBase + r, kcol = kk + k;
            uint32_t sz = (row < N && kcol < F) ? 4u : 0u;
            const float* src = x + (uint64_t)(row < N ? row : 0) * F
                                 + (kcol < F ? kcol : 0);
            uint32_t dst = sb + A_OFF[buf]
                         + (uint32_t)(r * 128 + (((k >> 2) ^ (r & 7)) << 4) + (k & 3) * 4);
            cp4(dst, src, sz);
        }
        // B tiles: 80 rows x 32 floats, hi+lo, 16B-aligned padded sources.
        #pragma unroll
        for (int i = 0; i < 3; i++) {
            int q = tid + i * 256;
            if (q < 640) {
                int n = q >> 3, g = q & 7;
                uint32_t doff = (uint32_t)(n * 128 + ((g ^ (n & 7)) << 4));
                const float* sh = g_w1bh + n * FP + kk + g * 4;
                const float* sl = g_w1bl + n * FP + kk + g * 4;
                cp16(sb + BH_OFF[buf] + doff, sh);
                cp16(sb + BL_OFF[buf] + doff, sl);
            }
        }
    };

    auto compute = [&](int buf) {
        const char* A  = smem + A_OFF[buf];
        const char* BH = smem + BH_OFF[buf];
        const char* BL = smem + BL_OFF[buf];
        #pragma unroll
        for (int s = 0; s < 4; s++) {
            const uint32_t sw0 = (uint32_t)(((2 * s) ^ gr) << 4) + tg * 4;
            const uint32_t sw1 = (uint32_t)(((2 * s + 1) ^ gr) << 4) + tg * 4;
            uint32_t ah[2][4], al[2][4];
            #pragma unroll
            for (int mt = 0; mt < 2; mt++) {
                int r0 = mg * 32 + mt * 16 + gr;
                float av[4];
                av[0] = *(const float*)(A + r0 * 128 + sw0);
                av[1] = *(const float*)(A + (r0 + 8) * 128 + sw0);
                av[2] = *(const float*)(A + r0 * 128 + sw1);
                av[3] = *(const float*)(A + (r0 + 8) * 128 + sw1);
                #pragma unroll
                for (int j = 0; j < 4; j++) {
                    ah[mt][j] = f2tf32(av[j]);
                    al[mt][j] = __float_as_uint(av[j] - __uint_as_float(ah[mt][j]));
                }
            }
            #pragma unroll
            for (int nt = 0; nt < 5; nt++) {
                int n0 = ng * 40 + nt * 8 + gr;
                uint32_t bh[2], bl[2];
                bh[0] = *(const uint32_t*)(BH + n0 * 128 + sw0);
                bh[1] = *(const uint32_t*)(BH + n0 * 128 + sw1);
                bl[0] = *(const uint32_t*)(BL + n0 * 128 + sw0);
                bl[1] = *(const uint32_t*)(BL + n0 * 128 + sw1);
                #pragma unroll
                for (int mt = 0; mt < 2; mt++) {
                    mma_tf32(acc[mt][nt], ah[mt], bh);   // hi*hi
                    mma_tf32(acc[mt][nt], al[mt], bh);   // lo*hi
                    mma_tf32(acc[mt][nt], ah[mt], bl);   // hi*lo
                }
            }
        }
    };

    fetch(0, 0);
    asm volatile("cp.async.commit_group;" ::: "memory");
    for (int c = 0; c < KCH; c++) {
        int buf = c & 1;
        if (c + 1 < KCH) {
            fetch(c + 1, buf ^ 1);
            asm volatile("cp.async.commit_group;" ::: "memory");
            asm volatile("cp.async.wait_group 1;" ::: "memory");
        } else {
            asm volatile("cp.async.wait_group 0;" ::: "memory");
        }
        __syncthreads();
        compute(buf);
        __syncthreads();
    }

    // epilogue: scale by dinv[row], store 67 of 80 cols
    #pragma unroll
    for (int mt = 0; mt < 2; mt++) {
        int r0 = rowBase + mg * 32 + mt * 16 + gr;
        float dv0 = (r0 < N)     ? g_dinv[r0]     : 0.f;
        float dv1 = (r0 + 8 < N) ? g_dinv[r0 + 8] : 0.f;
        #pragma unroll
        for (int nt = 0; nt < 5; nt++) {
            int cb = ng * 40 + nt * 8 + tg * 2;
            #pragma unroll
            for (int e = 0; e < 2; e++) {
                int colj = cb + e;
                if (colj < H) {
                    if (r0 < N)     g_h1s[r0 * H + colj]       = acc[mt][nt][e]     * dv0;
                    if (r0 + 8 < N) g_h1s[(r0 + 8) * H + colj] = acc[mt][nt][e + 2] * dv1;
                }
            }
        }
    }
}

// ---------------- aggregate layer 1 (+b1, leaky_relu) ----------------
// one warp per node; unrolled x4 neighbor loop for MLP
__global__ __launch_bounds__(256) void agg1_kernel(const float* __restrict__ b1) {
    int warp = (blockIdx.x * 256 + threadIdx.x) >> 5;
    if (warp >= N) return;
    int lane = threadIdx.x & 31;

    const float* hs = g_h1s + (size_t)warp * H;
    float s0 = hs[lane];
    float s1 = hs[lane + 32];
    float s2 = (lane < 3) ? hs[lane + 64] : 0.f;

    int n = g_cnt[warp];
    const int* rp = g_rows + g_start[warp];
    int k = 0;
    for (; k + 4 <= n; k += 4) {
        int r0 = rp[k], r1 = rp[k + 1], r2 = rp[k + 2], r3 = rp[k + 3];
        const float* h0 = g_h1s + (size_t)r0 * H;
        const float* h1 = g_h1s + (size_t)r1 * H;
        const float* h2 = g_h1s + (size_t)r2 * H;
        const float* h3 = g_h1s + (size_t)r3 * H;
        float t00 = h0[lane],      t10 = h1[lane],      t20 = h2[lane],      t30 = h3[lane];
        float t01 = h0[lane + 32], t11 = h1[lane + 32], t21 = h2[lane + 32], t31 = h3[lane + 32];
        s0 += (t00 + t10) + (t20 + t30);
        s1 += (t01 + t11) + (t21 + t31);
        if (lane < 3)
            s2 += (h0[lane + 64] + h1[lane + 64]) + (h2[lane + 64] + h3[lane + 64]);
    }
    for (; k < n; k++) {
        int r = rp[k];
        const float* hr = g_h1s + (size_t)r * H;
        s0 += hr[lane];
        s1 += hr[lane + 32];
        if (lane < 3) s2 += hr[lane + 64];
    }
    float dv = g_dinv[warp];
    float* out = g_a1 + (size_t)warp * H;
    float v;
    v = fmaf(dv, s0, b1[lane]);      out[lane]      = (v > 0.f) ? v : 0.01f * v;
    v = fmaf(dv, s1, b1[lane + 32]); out[lane + 32] = (v > 0.f) ? v : 0.01f * v;
    if (lane < 3) {
        v = fmaf(dv, s2, b1[lane + 64]); out[lane + 64] = (v > 0.f) ? v : 0.01f * v;
    }
}

// ---------------- GEMM2: h2s = (a1 @ W2) * dinv ----------------
__global__ __launch_bounds__(128) void gemm2_kernel(const float* __restrict__ W2) {
    __shared__ float as[128 * H];
    __shared__ float w[H * C];
    int tid = threadIdx.x;
    int base = blockIdx.x * 128;
    int nn = N - base; if (nn > 128) nn = 128;
    int total = nn * H;
    for (int i = tid; i < total; i += 128) as[i] = g_a1[(size_t)base * H + i];
    for (int i = tid; i < H * C; i += 128) w[i] = W2[i];
    __syncthreads();
    if (tid < nn) {
        float acc[C];
        #pragma unroll
        for (int j = 0; j < C; j++) acc[j] = 0.f;
        const float* ar = as + tid * H;
        #pragma unroll 4
        for (int k = 0; k < H; k++) {
            float av = ar[k];
            #pragma unroll
            for (int j = 0; j < C; j++) acc[j] = fmaf(av, w[k * C + j], acc[j]);
        }
        int node = base + tid;
        float dv = g_dinv[node];
        #pragma unroll
        for (int j = 0; j < C; j++) g_h2s[node * C + j] = acc[j] * dv;
    }
}

// ---------------- aggregate layer 2 + b2 + log_softmax ----------------
__global__ __launch_bounds__(256) void agg2_kernel(const float* __restrict__ b2,
                                                   float* __restrict__ out) {
    int warp = (blockIdx.x * 256 + threadIdx.x) >> 5;
    int lane = threadIdx.x & 31;
    int g = lane >> 3, j = lane & 7;
    int n = warp * 4 + g;

    float acc = (j < C) ? g_h2s[n * C + j] : 0.f;
    int sbeg = g_start[n], c = g_cnt[n];
    const int* rp = g_rows + sbeg;
    for (int k = 0; k < c; k++) {
        int r = rp[k];
        if (j < C) acc += g_h2s[r * C + j];
    }
    float logit = (j < C) ? fmaf(g_dinv[n], acc, b2[j]) : -3.0e38f;

    float m = logit;
    #pragma unroll
    for (int o = 4; o > 0; o >>= 1)
        m = fmaxf(m, __shfl_xor_sync(0xffffffffu, m, o, 8));
    float ex = (j < C) ? expf(logit - m) : 0.f;
    float sum = ex;
    #pragma unroll
    for (int o = 4; o > 0; o >>= 1)
        sum += __shfl_xor_sync(0xffffffffu, sum, o, 8);
    if (j < C) out[n * C + j] = logit - m - logf(sum);
}

// ---------------- launch ----------------
extern "C" void kernel_launch(void* const* d_in, const int* in_sizes, int n_in,
                              void* d_out, int out_size) {
    const float* x    = (const float*)d_in[0];
    const int*   ei   = (const int*)d_in[1];
    const float* W1   = (const float*)d_in[2];
    const float* b1   = (const float*)d_in[3];
    const float* W2   = (const float*)d_in[4];
    const float* b2   = (const float*)d_in[5];
    float*       out  = (float*)d_out;

    const int* row = ei;
    const int* col = ei + E;

    int nB = (N + 255) / 256;
    int eB = (E + 255) / 256;
    int sB = (N + 1023) / 1024;

    const int GEMM1_SMEM = 73728;
    cudaFuncSetAttribute(gemm1_mma, cudaFuncAttributeMaxDynamicSharedMemorySize,
                         GEMM1_SMEM);

    w1split_kernel<<<(BN * FP + 255) / 256, 256>>>(W1);
    zero_cnt_kernel<<<nB, 256>>>();
    hist_kernel<<<eB, 256>>>(col);
    scan1_kernel<<<sB, 1024>>>();
    scan2_kernel<<<1, 128>>>(sB);
    scan3_kernel<<<nB, 256>>>();
    fill_kernel<<<eB, 256>>>(row, col);

    gemm1_mma<<<(N + 127) / 128, 256, GEMM1_SMEM>>>(x);
    agg1_kernel<<<(N * 32 + 255) / 256, 256>>>(b1);
    gemm2_kernel<<<(N + 127) / 128, 128>>>(W2);
    agg2_kernel<<<(N * 8 + 255) / 256, 256>>>(b2, out);
}

// round 12
// speedup vs baseline: 1.8134x; 1.1796x over previous
#include <cuda_runtime.h>
#include <cuda_bf16.h>
#include <cstdint>

// Problem constants (fixed by the reference)
constexpr int N  = 100000;   // nodes
constexpr int F  = 1433;     // input features
constexpr int H  = 67;       // hidden
constexpr int C  = 7;        // classes
constexpr int E  = 3200000;  // edges

constexpr int BN = 80;       // H padded to 80 (10 n-tiles of 8, splits 2-ways)
constexpr int FP = 1440;     // F padded to multiple of 32
constexpr int KCH = FP / 32; // 45 K-chunks of 32
constexpr int HS = 72;       // h1s row stride (288B, 32B-aligned sectors)

// ---------------- scratch (no allocations allowed) ----------------
__device__ float g_h1s[N * HS];    // raw x@W1 (no dinv), padded stride
__device__ float g_a1 [N * H];     // post-aggregate, +b1, leaky_relu
__device__ float g_h2s[N * C];     // (a1@W2) * dinv[row]
__device__ float g_dinv[N];
__device__ int   g_cnt[N];
__device__ int   g_start[N];
__device__ int   g_cursor[N];
__device__ int   g_rows[E];
__device__ int   g_bsums[128];
__device__ __nv_bfloat16 g_w1bh[BN * FP];  // W1^T hi bf16, k-major, zero padded
__device__ __nv_bfloat16 g_w1bl[BN * FP];  // W1^T lo residual bf16

// ---------------- helpers ----------------
__device__ __forceinline__ uint32_t smem_to_u32(const void* p) {
    uint32_t a;
    asm("{ .reg .u64 t; cvta.to.shared.u64 t, %1; cvt.u32.u64 %0, t; }"
        : "=r"(a) : "l"(p));
    return a;
}
__device__ __forceinline__ void cp4(uint32_t dst, const void* src, uint32_t sz) {
    asm volatile("cp.async.ca.shared.global [%0], [%1], 4, %2;"
                 :: "r"(dst), "l"(src), "r"(sz) : "memory");
}
__device__ __forceinline__ void cp8(uint32_t dst, const void* src) {
    asm volatile("cp.async.ca.shared.global [%0], [%1], 8;"
                 :: "r"(dst), "l"(src) : "memory");
}
__device__ __forceinline__ void mma_bf16(float* d, const uint32_t* a, const uint32_t* b) {
    asm volatile(
        "mma.sync.aligned.m16n8k16.row.col.f32.bf16.bf16.f32 "
        "{%0,%1,%2,%3}, {%4,%5,%6,%7}, {%8,%9}, {%0,%1,%2,%3};"
        : "+f"(d[0]), "+f"(d[1]), "+f"(d[2]), "+f"(d[3])
        : "r"(a[0]), "r"(a[1]), "r"(a[2]), "r"(a[3]), "r"(b[0]), "r"(b[1]));
}
// split f32 pair (p.x = k even elem, p.y = k odd elem) into bf16x2 hi + lo packs
__device__ __forceinline__ void bsplit(float2 p, uint32_t& hi, uint32_t& lo) {
    asm("cvt.rn.bf16x2.f32 %0, %1, %2;" : "=r"(hi) : "f"(p.y), "f"(p.x));
    float h0 = __uint_as_float(hi << 16);
    float h1 = __uint_as_float(hi & 0xFFFF0000u);
    float l0 = p.x - h0;
    float l1 = p.y - h1;
    asm("cvt.rn.bf16x2.f32 %0, %1, %2;" : "=r"(lo) : "f"(l1), "f"(l0));
}

// ---------------- W1 transpose + bf16 split:  [n][k], zero padded ----------------
__global__ void w1split_kernel(const float* __restrict__ W1) {
    int i = blockIdx.x * 256 + threadIdx.x;
    if (i < BN * FP) {
        int n = i / FP, k = i - n * FP;
        float w = (n < H && k < F) ? W1[k * H + n] : 0.f;
        __nv_bfloat16 wh = __float2bfloat16_rn(w);
        g_w1bh[i] = wh;
        g_w1bl[i] = __float2bfloat16_rn(w - __bfloat162float(wh));
    }
}

// ---------------- degree / CSR construction ----------------
__global__ void zero_cnt_kernel() {
    int i = blockIdx.x * blockDim.x + threadIdx.x;
    if (i < N) g_cnt[i] = 0;
}
__global__ void hist_kernel(const int* __restrict__ col) {
    int e = blockIdx.x * blockDim.x + threadIdx.x;
    if (e < E) atomicAdd(&g_cnt[col[e]], 1);
}
__global__ __launch_bounds__(1024) void scan1_kernel() {
    __shared__ int s[1024];
    int i = blockIdx.x * 1024 + threadIdx.x;
    int v = (i < N) ? g_cnt[i] : 0;
    s[threadIdx.x] = v;
    __syncthreads();
    #pragma unroll
    for (int off = 1; off < 1024; off <<= 1) {
        int t = 0;
        if ((int)threadIdx.x >= off) t = s[threadIdx.x - off];
        __syncthreads();
        s[threadIdx.x] += t;
        __syncthreads();
    }
    if (i < N) g_start[i] = s[threadIdx.x] - v;
    if (threadIdx.x == 1023) g_bsums[blockIdx.x] = s[1023];
}
__global__ void scan2_kernel(int nblocks) {
    __shared__ int s[128];
    if ((int)threadIdx.x < nblocks) s[threadIdx.x] = g_bsums[threadIdx.x];
    __syncthreads();
    if (threadIdx.x == 0) {
        int run = 0;
        for (int b = 0; b < nblocks; b++) { int t = s[b]; s[b] = run; run += t; }
    }
    __syncthreads();
    if ((int)threadIdx.x < nblocks) g_bsums[threadIdx.x] = s[threadIdx.x];
}
__global__ void scan3_kernel() {
    int i = blockIdx.x * blockDim.x + threadIdx.x;
    if (i < N) {
        int st = g_start[i] + g_bsums[i >> 10];
        g_start[i]  = st;
        g_cursor[i] = st;
        g_dinv[i]   = rsqrtf((float)(g_cnt[i] + 1));
    }
}
__global__ void fill_kernel(const int* __restrict__ row, const int* __restrict__ col) {
    int e = blockIdx.x * blockDim.x + threadIdx.x;
    if (e < E) {
        int c = col[e];
        int p = atomicAdd(&g_cursor[c], 1);
        g_rows[p] = row[e];
    }
}

// ---------------- GEMM1 (mma.sync bf16 2-split): h1s = x @ W1 (raw) ----------
// CTA: 128 rows x 80 cols (72 written), K in chunks of 32, cp.async double buffer.
// 8 warps: mg = wid>>1 -> 32-row slab (2 m16 frags), ng = wid&1 -> 40 cols
// (5 n8 tiles). Per warp per k16: 30 HMMA, 8 LDS.64 (A f32), 20 LDS.32 (B bf16).
// A split to bf16 hi/lo in registers; B pre-split in global (w1split_kernel).
// SMEM (53248 B): A0@0 A1@16384 (f32, 16KB, 16B-granule XOR swizzle),
//   BH0@32768 BL0@37888 BH1@43008 BL1@48128 (bf16, 5120B each, 8B-granule XOR).
__global__ __launch_bounds__(256, 2) void gemm1_mma(const float* __restrict__ x) {
    extern __shared__ char smem[];
    const uint32_t sb = smem_to_u32(smem);
    const int tid = threadIdx.x;
    const int wid = tid >> 5, lane = tid & 31;
    const int gr = lane >> 2, tg = lane & 3;
    const int mg = wid >> 1, ng = wid & 1;
    const int rowBase = blockIdx.x * 128;

    const uint32_t A_OFF[2]  = {0u, 16384u};
    const uint32_t BH_OFF[2] = {32768u, 43008u};
    const uint32_t BL_OFF[2] = {37888u, 48128u};

    float acc[2][5][4];
    #pragma unroll
    for (int mt = 0; mt < 2; mt++)
        #pragma unroll
        for (int nt = 0; nt < 5; nt++)
            #pragma unroll
            for (int e = 0; e < 4; e++) acc[mt][nt][e] = 0.f;

    auto fetch = [&](int c, int buf) {
        const int kk = c * 32;
        // A tile: 128 rows x 32 f32. x rows only 4B-aligned -> 4B cp.async.
        #pragma unroll
        for (int i = 0; i < 16; i++) {
            int q = tid + i * 256;                 // 0..4095
            int r = q >> 5, k = q & 31;
            int row = rowBase + r, kcol = kk + k;
            uint32_t sz = (row < N && kcol < F) ? 4u : 0u;
            const float* src = x + (uint64_t)(row < N ? row : 0) * F
                                 + (kcol < F ? kcol : 0);
            uint32_t dst = sb + A_OFF[buf]
                         + (uint32_t)(r * 128 + (((k >> 2) ^ (r & 7)) << 4) + (k & 3) * 4);
            cp4(dst, src, sz);
        }
        // B tiles: 80 n-rows x 32 k bf16 (64B/row), hi+lo, 8B chunks w/ XOR swizzle
        #pragma unroll
        for (int i = 0; i < 3; i++) {
            int q = tid + i * 256;
            if (q < 640) {
                int n = q >> 3, g = q & 7;
                uint32_t doff = (uint32_t)(n * 64 + ((g ^ (n & 7)) << 3));
                const __nv_bfloat16* sh = g_w1bh + n * FP + kk + g * 4;
                const __nv_bfloat16* sl = g_w1bl + n * FP + kk + g * 4;
                cp8(sb + BH_OFF[buf] + doff, sh);
                cp8(sb + BL_OFF[buf] + doff, sl);
            }
        }
    };

    auto offA = [&](int r, int k) -> uint32_t {
        return (uint32_t)(r * 128 + (((k >> 2) ^ (r & 7)) << 4) + (k & 3) * 4);
    };

    auto compute = [&](int buf) {
        const char* A  = smem + A_OFF[buf];
        const char* BH = smem + BH_OFF[buf];
        const char* BL = smem + BL_OFF[buf];
        #pragma unroll
        for (int s = 0; s < 2; s++) {          // two k16 steps per 32-chunk
            const int kp0 = 16 * s + 2 * tg;   // even -> f32 pair in one granule
            const int kp1 = kp0 + 8;
            uint32_t ah[2][4], al[2][4];
            #pragma unroll
            for (int mt = 0; mt < 2; mt++) {
                int r0 = mg * 32 + mt * 16 + gr;
                float2 p0 = *(const float2*)(A + offA(r0,     kp0));
                float2 p1 = *(const float2*)(A + offA(r0 + 8, kp0));
                float2 p2 = *(const float2*)(A + offA(r0,     kp1));
                float2 p3 = *(const float2*)(A + offA(r0 + 8, kp1));
                bsplit(p0, ah[mt][0], al[mt][0]);
                bsplit(p1, ah[mt][1], al[mt][1]);
                bsplit(p2, ah[mt][2], al[mt][2]);
                bsplit(p3, ah[mt][3], al[mt][3]);
            }
            // B fragment byte offsets within 64B bf16 row, 8B-granule XOR swizzle
            const int kb  = 32 * s + 4 * tg;          // byte of k=16s+2tg
            const int g0  = kb >> 3;                  // granule idx
            const int rem = kb & 7;                   // 0 or 4
            #pragma unroll
            for (int nt = 0; nt < 5; nt++) {
                int n0 = ng * 40 + nt * 8 + gr;
                uint32_t a0 = (uint32_t)(n0 * 64 + (( g0      ^ (n0 & 7)) << 3) + rem);
                uint32_t a1 = (uint32_t)(n0 * 64 + (((g0 + 2) ^ (n0 & 7)) << 3) + rem);
                uint32_t bh[2], bl[2];
                bh[0] = *(const uint32_t*)(BH + a0);
                bh[1] = *(const uint32_t*)(BH + a1);
                bl[0] = *(const uint32_t*)(BL + a0);
                bl[1] = *(const uint32_t*)(BL + a1);
                #pragma unroll
                for (int mt = 0; mt < 2; mt++) {
                    mma_bf16(acc[mt][nt], ah[mt], bh);   // hi*hi
                    mma_bf16(acc[mt][nt], al[mt], bh);   // lo*hi
                    mma_bf16(acc[mt][nt], ah[mt], bl);   // hi*lo
                }
            }
        }
    };

    fetch(0, 0);
    asm volatile("cp.async.commit_group;" ::: "memory");
    for (int c = 0; c < KCH; c++) {
        int buf = c & 1;
        if (c + 1 < KCH) {
            fetch(c + 1, buf ^ 1);
            asm volatile("cp.async.commit_group;" ::: "memory");
            asm volatile("cp.async.wait_group 1;" ::: "memory");
        } else {
            asm volatile("cp.async.wait_group 0;" ::: "memory");
        }
        __syncthreads();
        compute(buf);
        __syncthreads();
    }

    // epilogue: store raw (dinv deferred to agg1), padded stride HS=72
    #pragma unroll
    for (int mt = 0; mt < 2; mt++) {
        int r0 = rowBase + mg * 32 + mt * 16 + gr;
        #pragma unroll
        for (int nt = 0; nt < 5; nt++) {
            int cb = ng * 40 + nt * 8 + tg * 2;
            #pragma unroll
            for (int e = 0; e < 2; e++) {
                int colj = cb + e;
                if (colj < HS) {
                    if (r0 < N)     g_h1s[r0 * HS + colj]       = acc[mt][nt][e];
                    if (r0 + 8 < N) g_h1s[(r0 + 8) * HS + colj] = acc[mt][nt][e + 2];
                }
            }
        }
    }
}

// ---------------- aggregate layer 1 (dinv folded here, +b1, leaky_relu) -------
// one warp per node; unrolled x4 neighbor loop for MLP
__global__ __launch_bounds__(256) void agg1_kernel(const float* __restrict__ b1) {
    int warp = (blockIdx.x * 256 + threadIdx.x) >> 5;
    if (warp >= N) return;
    int lane = threadIdx.x & 31;

    const float* hs = g_h1s + (size_t)warp * HS;
    float dvw = g_dinv[warp];
    float s0 = hs[lane] * dvw;
    float s1 = hs[lane + 32] * dvw;
    float s2 = (lane < 3) ? hs[lane + 64] * dvw : 0.f;

    int n = g_cnt[warp];
    const int* rp = g_rows + g_start[warp];
    int k = 0;
    for (; k + 4 <= n; k += 4) {
        int r0 = rp[k], r1 = rp[k + 1], r2 = rp[k + 2], r3 = rp[k + 3];
        float d0 = g_dinv[r0], d1 = g_dinv[r1], d2 = g_dinv[r2], d3 = g_dinv[r3];
        const float* h0 = g_h1s + (size_t)r0 * HS;
        const float* h1 = g_h1s + (size_t)r1 * HS;
        const float* h2 = g_h1s + (size_t)r2 * HS;
        const float* h3 = g_h1s + (size_t)r3 * HS;
        s0 = fmaf(h0[lane], d0, s0);
        s0 = fmaf(h1[lane], d1, s0);
        s0 = fmaf(h2[lane], d2, s0);
        s0 = fmaf(h3[lane], d3, s0);
        s1 = fmaf(h0[lane + 32], d0, s1);
        s1 = fmaf(h1[lane + 32], d1, s1);
        s1 = fmaf(h2[lane + 32], d2, s1);
        s1 = fmaf(h3[lane + 32], d3, s1);
        if (lane < 3) {
            s2 = fmaf(h0[lane + 64], d0, s2);
            s2 = fmaf(h1[lane + 64], d1, s2);
            s2 = fmaf(h2[lane + 64], d2, s2);
            s2 = fmaf(h3[lane + 64], d3, s2);
        }
    }
    for (; k < n; k++) {
        int r = rp[k];
        float dr = g_dinv[r];
        const float* hr = g_h1s + (size_t)r * HS;
        s0 = fmaf(hr[lane], dr, s0);
        s1 = fmaf(hr[lane + 32], dr, s1);
        if (lane < 3) s2 = fmaf(hr[lane + 64], dr, s2);
    }
    float* out = g_a1 + (size_t)warp * H;
    float v;
    v = fmaf(dvw, s0, b1[lane]);      out[lane]      = (v > 0.f) ? v : 0.01f * v;
    v = fmaf(dvw, s1, b1[lane + 32]); out[lane + 32] = (v > 0.f) ? v : 0.01f * v;
    if (lane < 3) {
        v = fmaf(dvw, s2, b1[lane + 64]); out[lane + 64] = (v > 0.f) ? v : 0.01f * v;
    }
}

// ---------------- GEMM2: h2s = (a1 @ W2) * dinv ----------------
__global__ __launch_bounds__(128) void gemm2_kernel(const float* __restrict__ W2) {
    __shared__ float as[128 * H];
    __shared__ float w[H * C];
    int tid = threadIdx.x;
    int base = blockIdx.x * 128;
    int nn = N - base; if (nn > 128) nn = 128;
    int total = nn * H;
    for (int i = tid; i < total; i += 128) as[i] = g_a1[(size_t)base * H + i];
    for (int i = tid; i < H * C; i += 128) w[i] = W2[i];
    __syncthreads();
    if (tid < nn) {
        float acc[C];
        #pragma unroll
        for (int j = 0; j < C; j++) acc[j] = 0.f;
        const float* ar = as + tid * H;
        #pragma unroll 4
        for (int k = 0; k < H; k++) {
            float av = ar[k];
            #pragma unroll
            for (int j = 0; j < C; j++) acc[j] = fmaf(av, w[k * C + j], acc[j]);
        }
        int node = base + tid;
        float dv = g_dinv[node];
        #pragma unroll
        for (int j = 0; j < C; j++) g_h2s[node * C + j] = acc[j] * dv;
    }
}

// ---------------- aggregate layer 2 + b2 + log_softmax ----------------
__global__ __launch_bounds__(256) void agg2_kernel(const float* __restrict__ b2,
                                                   float* __restrict__ out) {
    int warp = (blockIdx.x * 256 + threadIdx.x) >> 5;
    int lane = threadIdx.x & 31;
    int g = lane >> 3, j = lane & 7;
    int n = warp * 4 + g;

    float acc = (j < C) ? g_h2s[n * C + j] : 0.f;
    int sbeg = g_start[n], c = g_cnt[n];
    const int* rp = g_rows + sbeg;
    for (int k = 0; k < c; k++) {
        int r = rp[k];
        if (j < C) acc += g_h2s[r * C + j];
    }
    float logit = (j < C) ? fmaf(g_dinv[n], acc, b2[j]) : -3.0e38f;

    float m = logit;
    #pragma unroll
    for (int o = 4; o > 0; o >>= 1)
        m = fmaxf(m, __shfl_xor_sync(0xffffffffu, m, o, 8));
    float ex = (j < C) ? expf(logit - m) : 0.f;
    float sum = ex;
    #pragma unroll
    for (int o = 4; o > 0; o >>= 1)
        sum += __shfl_xor_sync(0xffffffffu, sum, o, 8);
    if (j < C) out[n * C + j] = logit - m - logf(sum);
}

// ---------------- launch ----------------
extern "C" void kernel_launch(void* const* d_in, const int* in_sizes, int n_in,
                              void* d_out, int out_size) {
    const float* x    = (const float*)d_in[0];
    const int*   ei   = (const int*)d_in[1];
    const float* W1   = (const float*)d_in[2];
    const float* b1   = (const float*)d_in[3];
    const float* W2   = (const float*)d_in[4];
    const float* b2   = (const float*)d_in[5];
    float*       out  = (float*)d_out;

    const int* row = ei;
    const int* col = ei + E;

    int nB = (N + 255) / 256;
    int eB = (E + 255) / 256;
    int sB = (N + 1023) / 1024;

    const int GEMM1_SMEM = 53248;
    cudaFuncSetAttribute(gemm1_mma, cudaFuncAttributeMaxDynamicSharedMemorySize,
                         GEMM1_SMEM);

    // gemm1 placed 4th so the profiler (empirically captures launch #4) sees it.
    w1split_kernel<<<(BN * FP + 255) / 256, 256>>>(W1);
    zero_cnt_kernel<<<nB, 256>>>();
    hist_kernel<<<eB, 256>>>(col);
    gemm1_mma<<<(N + 127) / 128, 256, GEMM1_SMEM>>>(x);
    scan1_kernel<<<sB, 1024>>>();
    scan2_kernel<<<1, 128>>>(sB);
    scan3_kernel<<<nB, 256>>>();
    fill_kernel<<<eB, 256>>>(row, col);

    agg1_kernel<<<(N * 32 + 255) / 256, 256>>>(b1);
    gemm2_kernel<<<(N + 127) / 128, 128>>>(W2);
    agg2_kernel<<<(N * 8 + 255) / 256, 256>>>(b2, out);
}

// round 14
// speedup vs baseline: 2.0552x; 1.1333x over previous
#include <cuda_runtime.h>
#include <cuda_bf16.h>
#include <cstdint>

// Problem constants (fixed by the reference)
constexpr int N  = 100000;   // nodes
constexpr int F  = 1433;     // input features
constexpr int H  = 67;       // hidden
constexpr int C  = 7;        // classes
constexpr int E  = 3200000;  // edges

constexpr int BN = 80;       // H padded to 80 (10 n-tiles of 8, splits 2-ways)
constexpr int FP = 1440;     // F padded to multiple of 16
constexpr int KC16 = FP / 16;// 90 k-chunks of 16
constexpr int HS = 72;       // h1s row stride (288B, 32B-aligned sectors)

// ---------------- scratch (no allocations allowed) ----------------
__device__ float g_h1s[N * HS];    // raw x@W1 (no dinv), padded stride
__device__ float g_a1 [N * H];     // post-aggregate, +b1, leaky_relu
__device__ float g_h2s[N * C];     // (a1@W2) * dinv[row]
__device__ float g_dinv[N];
__device__ int   g_cnt[N];
__device__ int   g_start[N];
__device__ int   g_cursor[N];
__device__ int   g_rows[E];
__device__ int   g_bsums[128];
// W1^T packed in MMA B-fragment order: [n][chunk c][granule g=tg] 16B =
// [bh(k=2g,2g+1), bh(k=2g+8,2g+9), bl(2g,2g+1), bl(2g+8,2g+9)], k rel to c*16
__device__ uint4 g_w1p[BN * KC16 * 4];

// ---------------- helpers ----------------
__device__ __forceinline__ uint32_t smem_to_u32(const void* p) {
    uint32_t a;
    asm("{ .reg .u64 t; cvta.to.shared.u64 t, %1; cvt.u32.u64 %0, t; }"
        : "=r"(a) : "l"(p));
    return a;
}
__device__ __forceinline__ void cp4(uint32_t dst, const void* src, uint32_t sz) {
    asm volatile("cp.async.ca.shared.global [%0], [%1], 4, %2;"
                 :: "r"(dst), "l"(src), "r"(sz) : "memory");
}
__device__ __forceinline__ void cp16(uint32_t dst, const void* src) {
    asm volatile("cp.async.cg.shared.global [%0], [%1], 16;"
                 :: "r"(dst), "l"(src) : "memory");
}
__device__ __forceinline__ void mma_bf16(float* d, const uint32_t* a, const uint32_t* b) {
    asm volatile(
        "mma.sync.aligned.m16n8k16.row.col.f32.bf16.bf16.f32 "
        "{%0,%1,%2,%3}, {%4,%5,%6,%7}, {%8,%9}, {%0,%1,%2,%3};"
        : "+f"(d[0]), "+f"(d[1]), "+f"(d[2]), "+f"(d[3])
        : "r"(a[0]), "r"(a[1]), "r"(a[2]), "r"(a[3]), "r"(b[0]), "r"(b[1]));
}
// split f32 pair (p.x = k even elem, p.y = k odd elem) into bf16x2 hi + lo packs
__device__ __forceinline__ void bsplit(float2 p, uint32_t& hi, uint32_t& lo) {
    asm("cvt.rn.bf16x2.f32 %0, %1, %2;" : "=r"(hi) : "f"(p.y), "f"(p.x));
    float h0 = __uint_as_float(hi << 16);
    float h1 = __uint_as_float(hi & 0xFFFF0000u);
    float l0 = p.x - h0;
    float l1 = p.y - h1;
    asm("cvt.rn.bf16x2.f32 %0, %1, %2;" : "=r"(lo) : "f"(l1), "f"(l0));
}
__device__ __forceinline__ uint32_t packbf(float e, float o) {  // e->low, o->high
    __nv_bfloat162 t = __floats2bfloat162_rn(e, o);
    return *reinterpret_cast<uint32_t*>(&t);
}

// ---------------- W1 transpose + bf16 split into fragment-packed layout -------
__global__ void w1split_kernel(const float* __restrict__ W1) {
    int i = blockIdx.x * 256 + threadIdx.x;          // one uint4 per thread
    if (i >= BN * KC16 * 4) return;
    int n = i / (KC16 * 4);
    int rem = i - n * (KC16 * 4);
    int c = rem >> 2, g = rem & 3;
    int kb = c * 16 + 2 * g;
    float w[4], r[4];                                 // k = kb, kb+1, kb+8, kb+9
    int ks[4] = {kb, kb + 1, kb + 8, kb + 9};
    #pragma unroll
    for (int j = 0; j < 4; j++) {
        float v = (n < H && ks[j] < F) ? W1[ks[j] * H + n] : 0.f;
        __nv_bfloat16 vh = __float2bfloat16_rn(v);
        w[j] = __bfloat162float(vh);
        r[j] = v - w[j];
    }
    uint4 o;
    o.x = packbf(w[0], w[1]);
    o.y = packbf(w[2], w[3]);
    o.z = packbf(r[0], r[1]);
    o.w = packbf(r[2], r[3]);
    g_w1p[i] = o;
}

// ---------------- degree / CSR construction ----------------
__global__ void zero_cnt_kernel() {
    int i = blockIdx.x * blockDim.x + threadIdx.x;
    if (i < N) g_cnt[i] = 0;
}
__global__ void hist_kernel(const int* __restrict__ col) {
    int e = blockIdx.x * blockDim.x + threadIdx.x;
    if (e < E) atomicAdd(&g_cnt[col[e]], 1);
}
__global__ __launch_bounds__(1024) void scan1_kernel() {
    __shared__ int s[1024];
    int i = blockIdx.x * 1024 + threadIdx.x;
    int v = (i < N) ? g_cnt[i] : 0;
    s[threadIdx.x] = v;
    __syncthreads();
    #pragma unroll
    for (int off = 1; off < 1024; off <<= 1) {
        int t = 0;
        if ((int)threadIdx.x >= off) t = s[threadIdx.x - off];
        __syncthreads();
        s[threadIdx.x] += t;
        __syncthreads();
    }
    if (i < N) g_start[i] = s[threadIdx.x] - v;
    if (threadIdx.x == 1023) g_bsums[blockIdx.x] = s[1023];
}
__global__ void scan2_kernel(int nblocks) {
    __shared__ int s[128];
    if ((int)threadIdx.x < nblocks) s[threadIdx.x] = g_bsums[threadIdx.x];
    __syncthreads();
    if (threadIdx.x == 0) {
        int run = 0;
        for (int b = 0; b < nblocks; b++) { int t = s[b]; s[b] = run; run += t; }
    }
    __syncthreads();
    if ((int)threadIdx.x < nblocks) g_bsums[threadIdx.x] = s[threadIdx.x];
}
__global__ void scan3_kernel() {
    int i = blockIdx.x * blockDim.x + threadIdx.x;
    if (i < N) {
        int st = g_start[i] + g_bsums[i >> 10];
        g_start[i]  = st;
        g_cursor[i] = st;
        g_dinv[i]   = rsqrtf((float)(g_cnt[i] + 1));
    }
}
__global__ void fill_kernel(const int* __restrict__ row, const int* __restrict__ col) {
    int e = blockIdx.x * blockDim.x + threadIdx.x;
    if (e < E) {
        int c = col[e];
        int p = atomicAdd(&g_cursor[c], 1);
        g_rows[p] = row[e];
    }
}

// ---------------- GEMM1 (mma.sync bf16 2-split): h1s = x @ W1 (raw) ----------
// CTA: 128 rows x 80 cols, K in chunks of 16, 3-stage cp.async ring, 1 barrier
// per chunk. 8 warps: mg=wid>>1 -> 32-row slab (2 m16 frags), ng=wid&1 -> 40
// cols (5 n8 tiles). Per warp per k16: 30 HMMA, 8 LDS.64 (A), 5 LDS.128 (B).
// Stage (13312B): A @0 (128 rows x 64B, 16B-granule XOR-(r&3) swizzle),
// B @8192 (80 rows x 64B, fragment-packed, conflict-free without swizzle).
constexpr int G1_STAGE = 13312;
constexpr int G1_SMEM  = 3 * G1_STAGE;  // 39936
__global__ __launch_bounds__(256, 3) void gemm1_mma(const float* __restrict__ x) {
    extern __shared__ char smem[];
    const uint32_t sb = smem_to_u32(smem);
    const int tid = threadIdx.x;
    const int wid = tid >> 5, lane = tid & 31;
    const int gr = lane >> 2, tg = lane & 3;
    const int mg = wid >> 1, ng = wid & 1;
    const int rowBase = blockIdx.x * 128;

    float acc[2][5][4];
    #pragma unroll
    for (int mt = 0; mt < 2; mt++)
        #pragma unroll
        for (int nt = 0; nt < 5; nt++)
            #pragma unroll
            for (int e = 0; e < 4; e++) acc[mt][nt][e] = 0.f;

    auto fetch = [&](int c, int st) {
        const int kk = c * 16;
        const uint32_t base = sb + (uint32_t)st * G1_STAGE;
        // A tile: 128 rows x 16 f32 (4B cp.async; x rows only 4B-aligned)
        #pragma unroll
        for (int i = 0; i < 8; i++) {
            int q = tid + i * 256;                 // 0..2047
            int r = q >> 4, k = q & 15;
            int row = rowBase + r, kcol = kk + k;
            uint32_t sz = (row < N && kcol < F) ? 4u : 0u;
            const float* src = x + (uint64_t)(row < N ? row : 0) * F
                                 + (kcol < F ? kcol : 0);
            uint32_t dst = base
                         + (uint32_t)(r * 64 + (((k >> 2) ^ (r & 3)) << 4) + (k & 3) * 4);
            cp4(dst, src, sz);
        }
        // B tile: 80 rows x 4 granules of 16B, fragment-packed, direct copy
        #pragma unroll
        for (int i = 0; i < 2; i++) {
            int q = tid + i * 256;
            if (q < 320) {
                int n = q >> 2, g = q & 3;
                const uint4* src = g_w1p + (n * KC16 + c) * 4 + g;
                uint32_t dst = base + 8192u + (uint32_t)(n * 64 + g * 16);
                cp16(dst, src);
            }
        }
    };

    const uint32_t aHalf = (uint32_t)((tg & 1) * 8);
    const int gA = tg >> 1;

    auto compute = [&](int st) {
        const char* A = smem + (uint32_t)st * G1_STAGE;
        const char* B = A + 8192;
        uint32_t ah[2][4], al[2][4];
        #pragma unroll
        for (int mt = 0; mt < 2; mt++) {
            int r0 = mg * 32 + mt * 16 + gr;
            int r1 = r0 + 8;
            float2 p0 = *(const float2*)(A + r0 * 64 + (((gA    ) ^ (r0 & 3)) << 4) + aHalf);
            float2 p1 = *(const float2*)(A + r1 * 64 + (((gA    ) ^ (r1 & 3)) << 4) + aHalf);
            float2 p2 = *(const float2*)(A + r0 * 64 + (((gA + 2) ^ (r0 & 3)) << 4) + aHalf);
            float2 p3 = *(const float2*)(A + r1 * 64 + (((gA + 2) ^ (r1 & 3)) << 4) + aHalf);
            bsplit(p0, ah[mt][0], al[mt][0]);
            bsplit(p1, ah[mt][1], al[mt][1]);
            bsplit(p2, ah[mt][2], al[mt][2]);
            bsplit(p3, ah[mt][3], al[mt][3]);
        }
        #pragma unroll
        for (int nt = 0; nt < 5; nt++) {
            int n0 = ng * 40 + nt * 8 + gr;
            uint4 bb = *(const uint4*)(B + n0 * 64 + tg * 16);
            uint32_t bh[2] = {bb.x, bb.y};
            uint32_t bl[2] = {bb.z, bb.w};
            #pragma unroll
            for (int mt = 0; mt < 2; mt++) {
                mma_bf16(acc[mt][nt], ah[mt], bh);   // hi*hi
                mma_bf16(acc[mt][nt], al[mt], bh);   // lo*hi
                mma_bf16(acc[mt][nt], ah[mt], bl);   // hi*lo
            }
        }
    };

    fetch(0, 0);
    asm volatile("cp.async.commit_group;" ::: "memory");
    fetch(1, 1);
    asm volatile("cp.async.commit_group;" ::: "memory");
    for (int c = 0; c < KC16; c++) {
        if (c < KC16 - 1) {
            asm volatile("cp.async.wait_group 1;" ::: "memory");
        } else {
            asm volatile("cp.async.wait_group 0;" ::: "memory");
        }
        __syncthreads();
        int st = c % 3;
        compute(st);
        if (c + 2 < KC16) {
            fetch(c + 2, (c + 2) % 3);
            asm volatile("cp.async.commit_group;" ::: "memory");
        }
    }

    // epilogue: store raw (dinv deferred to agg1), padded stride HS=72
    #pragma unroll
    for (int mt = 0; mt < 2; mt++) {
        int r0 = rowBase + mg * 32 + mt * 16 + gr;
        #pragma unroll
        for (int nt = 0; nt < 5; nt++) {
            int cb = ng * 40 + nt * 8 + tg * 2;
            #pragma unroll
            for (int e = 0; e < 2; e++) {
                int colj = cb + e;
                if (colj < HS) {
                    if (r0 < N)     g_h1s[r0 * HS + colj]       = acc[mt][nt][e];
                    if (r0 + 8 < N) g_h1s[(r0 + 8) * HS + colj] = acc[mt][nt][e + 2];
                }
            }
        }
    }
}

// ---------------- aggregate layer 1 (dinv folded here, +b1, leaky_relu) -------
// one warp per node; unrolled x4 neighbor loop for MLP
__global__ __launch_bounds__(256) void agg1_kernel(const float* __restrict__ b1) {
    int warp = (blockIdx.x * 256 + threadIdx.x) >> 5;
    if (warp >= N) return;
    int lane = threadIdx.x & 31;

    const float* hs = g_h1s + (size_t)warp * HS;
    float dvw = g_dinv[warp];
    float s0 = hs[lane] * dvw;
    float s1 = hs[lane + 32] * dvw;
    float s2 = (lane < 3) ? hs[lane + 64] * dvw : 0.f;

    int n = g_cnt[warp];
    const int* rp = g_rows + g_start[warp];
    int k = 0;
    for (; k + 4 <= n; k += 4) {
        int r0 = rp[k], r1 = rp[k + 1], r2 = rp[k + 2], r3 = rp[k + 3];
        float d0 = g_dinv[r0], d1 = g_dinv[r1], d2 = g_dinv[r2], d3 = g_dinv[r3];
        const float* h0 = g_h1s + (size_t)r0 * HS;
        const float* h1 = g_h1s + (size_t)r1 * HS;
        const float* h2 = g_h1s + (size_t)r2 * HS;
        const float* h3 = g_h1s + (size_t)r3 * HS;
        s0 = fmaf(h0[lane], d0, s0);
        s0 = fmaf(h1[lane], d1, s0);
        s0 = fmaf(h2[lane], d2, s0);
        s0 = fmaf(h3[lane], d3, s0);
        s1 = fmaf(h0[lane + 32], d0, s1);
        s1 = fmaf(h1[lane + 32], d1, s1);
        s1 = fmaf(h2[lane + 32], d2, s1);
        s1 = fmaf(h3[lane + 32], d3, s1);
        if (lane < 3) {
            s2 = fmaf(h0[lane + 64], d0, s2);
            s2 = fmaf(h1[lane + 64], d1, s2);
            s2 = fmaf(h2[lane + 64], d2, s2);
            s2 = fmaf(h3[lane + 64], d3, s2);
        }
    }
    for (; k < n; k++) {
        int r = rp[k];
        float dr = g_dinv[r];
        const float* hr = g_h1s + (size_t)r * HS;
        s0 = fmaf(hr[lane], dr, s0);
        s1 = fmaf(hr[lane + 32], dr, s1);
        if (lane < 3) s2 = fmaf(hr[lane + 64], dr, s2);
    }
    float* out = g_a1 + (size_t)warp * H;
    float v;
    v = fmaf(dvw, s0, b1[lane]);      out[lane]      = (v > 0.f) ? v : 0.01f * v;
    v = fmaf(dvw, s1, b1[lane + 32]); out[lane + 32] = (v > 0.f) ? v : 0.01f * v;
    if (lane < 3) {
        v = fmaf(dvw, s2, b1[lane + 64]); out[lane + 64] = (v > 0.f) ? v : 0.01f * v;
    }
}

// ---------------- GEMM2: h2s = (a1 @ W2) * dinv ----------------
__global__ __launch_bounds__(128) void gemm2_kernel(const float* __restrict__ W2) {
    __shared__ float as[128 * H];
    __shared__ float w[H * C];
    int tid = threadIdx.x;
    int base = blockIdx.x * 128;
    int nn = N - base; if (nn > 128) nn = 128;
    int total = nn * H;
    for (int i = tid; i < total; i += 128) as[i] = g_a1[(size_t)base * H + i];
    for (int i = tid; i < H * C; i += 128) w[i] = W2[i];
    __syncthreads();
    if (tid < nn) {
        float acc[C];
        #pragma unroll
        for (int j = 0; j < C; j++) acc[j] = 0.f;
        const float* ar = as + tid * H;
        #pragma unroll 4
        for (int k = 0; k < H; k++) {
            float av = ar[k];
            #pragma unroll
            for (int j = 0; j < C; j++) acc[j] = fmaf(av, w[k * C + j], acc[j]);
        }
        int node = base + tid;
        float dv = g_dinv[node];
        #pragma unroll
        for (int j = 0; j < C; j++) g_h2s[node * C + j] = acc[j] * dv;
    }
}

// ---------------- aggregate layer 2 + b2 + log_softmax ----------------
__global__ __launch_bounds__(256) void agg2_kernel(const float* __restrict__ b2,
                                                   float* __restrict__ out) {
    int warp = (blockIdx.x * 256 + threadIdx.x) >> 5;
    int lane = threadIdx.x & 31;
    int g = lane >> 3, j = lane & 7;
    int n = warp * 4 + g;

    float acc = (j < C) ? g_h2s[n * C + j] : 0.f;
    int sbeg = g_start[n], c = g_cnt[n];
    const int* rp = g_rows + sbeg;
    for (int k = 0; k < c; k++) {
        int r = rp[k];
        if (j < C) acc += g_h2s[r * C + j];
    }
    float logit = (j < C) ? fmaf(g_dinv[n], acc, b2[j]) : -3.0e38f;

    float m = logit;
    #pragma unroll
    for (int o = 4; o > 0; o >>= 1)
        m = fmaxf(m, __shfl_xor_sync(0xffffffffu, m, o, 8));
    float ex = (j < C) ? expf(logit - m) : 0.f;
    float sum = ex;
    #pragma unroll
    for (int o = 4; o > 0; o >>= 1)
        sum += __shfl_xor_sync(0xffffffffu, sum, o, 8);
    if (j < C) out[n * C + j] = logit - m - logf(sum);
}

// ---------------- launch ----------------
extern "C" void kernel_launch(void* const* d_in, const int* in_sizes, int n_in,
                              void* d_out, int out_size) {
    const float* x    = (const float*)d_in[0];
    const int*   ei   = (const int*)d_in[1];
    const float* W1   = (const float*)d_in[2];
    const float* b1   = (const float*)d_in[3];
    const float* W2   = (const float*)d_in[4];
    const float* b2   = (const float*)d_in[5];
    float*       out  = (float*)d_out;

    const int* row = ei;
    const int* col = ei + E;

    int nB = (N + 255) / 256;
    int eB = (E + 255) / 256;
    int sB = (N + 1023) / 1024;

    cudaFuncSetAttribute(gemm1_mma, cudaFuncAttributeMaxDynamicSharedMemorySize,
                         G1_SMEM);

    // gemm1 placed 4th so the profiler (empirically captures launch #4) sees it.
    w1split_kernel<<<(BN * KC16 * 4 + 255) / 256, 256>>>(W1);
    zero_cnt_kernel<<<nB, 256>>>();
    hist_kernel<<<eB, 256>>>(col);
    gemm1_mma<<<(N + 127) / 128, 256, G1_SMEM>>>(x);
    scan1_kernel<<<sB, 1024>>>();
    scan2_kernel<<<1, 128>>>(sB);
    scan3_kernel<<<nB, 256>>>();
    fill_kernel<<<eB, 256>>>(row, col);

    agg1_kernel<<<(N * 32 + 255) / 256, 256>>>(b1);
    gemm2_kernel<<<(N + 127) / 128, 128>>>(W2);
    agg2_kernel<<<(N * 8 + 255) / 256, 256>>>(b2, out);
}

// round 17
// speedup vs baseline: 2.2815x; 1.1101x over previous
#include <cuda_runtime.h>
#include <cuda_bf16.h>
#include <cstdint>

// Problem constants (fixed by the reference)
constexpr int N  = 100000;   // nodes
constexpr int F  = 1433;     // input features
constexpr int H  = 67;       // hidden
constexpr int C  = 7;        // classes
constexpr int E  = 3200000;  // edges

constexpr int BN = 80;       // H padded to 80 (10 n-tiles of 8, splits 2-ways)
constexpr int FP = 1440;     // F padded to multiple of 16
constexpr int KC16 = FP / 16;// 90 k-chunks of 16
constexpr int HS = 72;       // h1s row stride (288B, 32B-aligned sectors)

// ---------------- scratch (no allocations allowed) ----------------
__device__ float g_h1s[N * HS];    // raw x@W1 (no dinv), padded stride
__device__ float g_a1 [N * H];     // post-aggregate, +b1, leaky_relu
__device__ float g_h2s[N * C];     // (a1@W2) * dinv[row]
__device__ float g_dinv[N];
__device__ int   g_cnt[N];
__device__ int   g_start[N];
__device__ int   g_cursor[N];
__device__ int   g_rows[E];
__device__ int   g_bsums[128];
// W1^T packed in MMA B-fragment order: [n][chunk c][granule g=tg] 16B =
// [bh(k=2g,2g+1), bh(k=2g+8,2g+9), bl(2g,2g+1), bl(2g+8,2g+9)], k rel to c*16
__device__ uint4 g_w1p[BN * KC16 * 4];

// ---------------- helpers ----------------
__device__ __forceinline__ uint32_t smem_to_u32(const void* p) {
    uint32_t a;
    asm("{ .reg .u64 t; cvta.to.shared.u64 t, %1; cvt.u32.u64 %0, t; }"
        : "=r"(a) : "l"(p));
    return a;
}
__device__ __forceinline__ void cp4(uint32_t dst, const void* src, uint32_t sz) {
    asm volatile("cp.async.ca.shared.global [%0], [%1], 4, %2;"
                 :: "r"(dst), "l"(src), "r"(sz) : "memory");
}
__device__ __forceinline__ void cp16(uint32_t dst, const void* src) {
    asm volatile("cp.async.cg.shared.global [%0], [%1], 16;"
                 :: "r"(dst), "l"(src) : "memory");
}
__device__ __forceinline__ void mma_bf16(float* d, const uint32_t* a, const uint32_t* b) {
    asm volatile(
        "mma.sync.aligned.m16n8k16.row.col.f32.bf16.bf16.f32 "
        "{%0,%1,%2,%3}, {%4,%5,%6,%7}, {%8,%9}, {%0,%1,%2,%3};"
        : "+f"(d[0]), "+f"(d[1]), "+f"(d[2]), "+f"(d[3])
        : "r"(a[0]), "r"(a[1]), "r"(a[2]), "r"(a[3]), "r"(b[0]), "r"(b[1]));
}
// split f32 pair (lo elem = k even, hi elem = k odd) into bf16x2 hi + lo packs
__device__ __forceinline__ void bsplit(float px, float py, uint32_t& hi, uint32_t& lo) {
    asm("cvt.rn.bf16x2.f32 %0, %1, %2;" : "=r"(hi) : "f"(py), "f"(px));
    float h0 = __uint_as_float(hi << 16);
    float h1 = __uint_as_float(hi & 0xFFFF0000u);
    float l0 = px - h0;
    float l1 = py - h1;
    asm("cvt.rn.bf16x2.f32 %0, %1, %2;" : "=r"(lo) : "f"(l1), "f"(l0));
}
__device__ __forceinline__ uint32_t packbf(float e, float o) {  // e->low, o->high
    __nv_bfloat162 t = __floats2bfloat162_rn(e, o);
    return *reinterpret_cast<uint32_t*>(&t);
}

// ---------------- W1 transpose + bf16 split into fragment-packed layout -------
__global__ void w1split_kernel(const float* __restrict__ W1) {
    int i = blockIdx.x * 256 + threadIdx.x;          // one uint4 per thread
    if (i >= BN * KC16 * 4) return;
    int n = i / (KC16 * 4);
    int rem = i - n * (KC16 * 4);
    int c = rem >> 2, g = rem & 3;
    int kb = c * 16 + 2 * g;
    float w[4], r[4];                                 // k = kb, kb+1, kb+8, kb+9
    int ks[4] = {kb, kb + 1, kb + 8, kb + 9};
    #pragma unroll
    for (int j = 0; j < 4; j++) {
        float v = (n < H && ks[j] < F) ? W1[ks[j] * H + n] : 0.f;
        __nv_bfloat16 vh = __float2bfloat16_rn(v);
        w[j] = __bfloat162float(vh);
        r[j] = v - w[j];
    }
    uint4 o;
    o.x = packbf(w[0], w[1]);
    o.y = packbf(w[2], w[3]);
    o.z = packbf(r[0], r[1]);
    o.w = packbf(r[2], r[3]);
    g_w1p[i] = o;
}

// ---------------- degree / CSR construction ----------------
__global__ void zero_cnt_kernel() {
    int i = blockIdx.x * blockDim.x + threadIdx.x;
    if (i < N) g_cnt[i] = 0;
}
__global__ void hist_kernel(const int* __restrict__ col) {
    int e = blockIdx.x * blockDim.x + threadIdx.x;
    if (e < E) atomicAdd(&g_cnt[col[e]], 1);
}
__global__ __launch_bounds__(1024) void scan1_kernel() {
    __shared__ int s[1024];
    int i = blockIdx.x * 1024 + threadIdx.x;
    int v = (i < N) ? g_cnt[i] : 0;
    s[threadIdx.x] = v;
    __syncthreads();
    #pragma unroll
    for (int off = 1; off < 1024; off <<= 1) {
        int t = 0;
        if ((int)threadIdx.x >= off) t = s[threadIdx.x - off];
        __syncthreads();
        s[threadIdx.x] += t;
        __syncthreads();
    }
    if (i < N) g_start[i] = s[threadIdx.x] - v;
    if (threadIdx.x == 1023) g_bsums[blockIdx.x] = s[1023];
}
__global__ void scan2_kernel(int nblocks) {
    __shared__ int s[128];
    if ((int)threadIdx.x < nblocks) s[threadIdx.x] = g_bsums[threadIdx.x];
    __syncthreads();
    if (threadIdx.x == 0) {
        int run = 0;
        for (int b = 0; b < nblocks; b++) { int t = s[b]; s[b] = run; run += t; }
    }
    __syncthreads();
    if ((int)threadIdx.x < nblocks) g_bsums[threadIdx.x] = s[threadIdx.x];
}
__global__ void scan3_kernel() {
    int i = blockIdx.x * blockDim.x + threadIdx.x;
    if (i < N) {
        int st = g_start[i] + g_bsums[i >> 10];
        g_start[i]  = st;
        g_cursor[i] = st;
        g_dinv[i]   = rsqrtf((float)(g_cnt[i] + 1));
    }
}
__global__ void fill_kernel(const int* __restrict__ row, const int* __restrict__ col) {
    int e = blockIdx.x * blockDim.x + threadIdx.x;
    if (e < E) {
        int c = col[e];
        int p = atomicAdd(&g_cursor[c], 1);
        g_rows[p] = row[e];
    }
}

// ---------------- GEMM1 (mma.sync bf16 2-split): h1s = x @ W1 (raw) ----------
// CTA: 128 rows x 80 cols, K in chunks of 16, 3-stage cp.async ring, 1 barrier
// per chunk. 8 warps: mg=wid>>1 -> 32-row slab (2 m16 frags), ng=wid&1 -> 40
// cols (5 n8 tiles). Per warp per k16: 30 HMMA, 4 LDS.128 (A), 5 LDS.128 (B).
// Stage (13312B): A @0 (128 rows x 64B, FRAGMENT-PACKED granules: granule g of
// a row = k{2g,2g+1,2g+8,2g+9} — conflict-free LDS.128, no swizzle needed),
// B @8192 (80 rows x 64B, fragment-packed hi/lo).
// Fetch addressing fully hoisted: one A pointer (+64B/chunk, 8 cp.async with
// constant 16*F-float immediate strides), one B pointer (+64B/chunk).
constexpr int G1_STAGE = 13312;
constexpr int G1_SMEM  = 3 * G1_STAGE;  // 39936
__global__ __launch_bounds__(256, 3) void gemm1_mma(const float* __restrict__ x) {
    extern __shared__ char smem[];
    const uint32_t sb = smem_to_u32(smem);
    const int tid = threadIdx.x;
    const int wid = tid >> 5, lane = tid & 31;
    const int gr = lane >> 2, tg = lane & 3;
    const int mg = wid >> 1, ng = wid & 1;
    const int rowBase = blockIdx.x * 128;
    const bool fast = (rowBase + 128 <= N);    // uniform per CTA

    // per-thread fetch geometry (chunk-invariant)
    const int r0t = tid >> 4, kt = tid & 15;
    const uint32_t aDstOff = (uint32_t)(r0t * 64
                         + (((kt & 7) >> 1) << 4)               // granule
                         + (((kt & 1) + ((kt >> 3) << 1)) << 2)); // pos
    const float* srcA = x + (size_t)(rowBase + r0t) * F + kt;   // deref iff fast
    const uint4* srcB = g_w1p + (tid >> 2) * (KC16 * 4) + (tid & 3);
    const uint32_t bDstOff = 8192u + (uint32_t)tid * 16u;
    const uint32_t szLast = (kt < 9) ? 4u : 0u;   // last chunk: k 1424+kt < 1433

    float acc[2][5][4];
    #pragma unroll
    for (int mt = 0; mt < 2; mt++)
        #pragma unroll
        for (int nt = 0; nt < 5; nt++)
            #pragma unroll
            for (int e = 0; e < 4; e++) acc[mt][nt][e] = 0.f;

    auto fetch = [&](int c, int st) {
        const uint32_t base = sb + (uint32_t)st * G1_STAGE;
        if (fast) {
            uint32_t sz = (c == KC16 - 1) ? szLast : 4u;
            const float* s = srcA;
            #pragma unroll
            for (int i = 0; i < 8; i++)
                cp4(base + aDstOff + (uint32_t)i * 1024u, s + (size_t)i * 16 * F, sz);
            srcA += 16;
        } else {
            const int kk = c * 16;
            #pragma unroll
            for (int i = 0; i < 8; i++) {
                int row = rowBase + r0t + i * 16, kcol = kk + kt;
                uint32_t sz = (row < N && kcol < F) ? 4u : 0u;
                const float* s = x + (size_t)(row < N ? row : 0) * F
                                   + (kcol < F ? kcol : 0);
                cp4(base + aDstOff + (uint32_t)i * 1024u, s, sz);
            }
        }
        cp16(base + bDstOff, srcB);
        if (tid < 64) cp16(base + bDstOff + 4096u, srcB + 64 * (KC16 * 4));
        srcB += 4;
    };

    auto compute = [&](int st) {
        const char* A = smem + (uint32_t)st * G1_STAGE;
        const char* B = A + 8192;
        uint32_t ah[2][4], al[2][4];
        #pragma unroll
        for (int mt = 0; mt < 2; mt++) {
            int r0 = mg * 32 + mt * 16 + gr;
            float4 q0 = *(const float4*)(A + r0 * 64 + tg * 16);
            float4 q1 = *(const float4*)(A + (r0 + 8) * 64 + tg * 16);
            bsplit(q0.x, q0.y, ah[mt][0], al[mt][0]);
            bsplit(q1.x, q1.y, ah[mt][1], al[mt][1]);
            bsplit(q0.z, q0.w, ah[mt][2], al[mt][2]);
            bsplit(q1.z, q1.w, ah[mt][3], al[mt][3]);
        }
        #pragma unroll
        for (int nt = 0; nt < 5; nt++) {
            int n0 = ng * 40 + nt * 8 + gr;
            uint4 bb = *(const uint4*)(B + n0 * 64 + tg * 16);
            uint32_t bh[2] = {bb.x, bb.y};
            uint32_t bl[2] = {bb.z, bb.w};
            #pragma unroll
            for (int mt = 0; mt < 2; mt++) {
                mma_bf16(acc[mt][nt], ah[mt], bh);   // hi*hi
                mma_bf16(acc[mt][nt], al[mt], bh);   // lo*hi
                mma_bf16(acc[mt][nt], ah[mt], bl);   // hi*lo
            }
        }
    };

    fetch(0, 0);
    asm volatile("cp.async.commit_group;" ::: "memory");
    fetch(1, 1);
    asm volatile("cp.async.commit_group;" ::: "memory");
    for (int c = 0; c < KC16; c++) {
        if (c < KC16 - 1) {
            asm volatile("cp.async.wait_group 1;" ::: "memory");
        } else {
            asm volatile("cp.async.wait_group 0;" ::: "memory");
        }
        __syncthreads();
        compute(c % 3);
        if (c + 2 < KC16) {
            fetch(c + 2, (c + 2) % 3);
            asm volatile("cp.async.commit_group;" ::: "memory");
        }
    }

    // epilogue: store raw (dinv deferred to agg1), padded stride HS=72
    #pragma unroll
    for (int mt = 0; mt < 2; mt++) {
        int r0 = rowBase + mg * 32 + mt * 16 + gr;
        #pragma unroll
        for (int nt = 0; nt < 5; nt++) {
            int cb = ng * 40 + nt * 8 + tg * 2;
            #pragma unroll
            for (int e = 0; e < 2; e++) {
                int colj = cb + e;
                if (colj < HS) {
                    if (r0 < N)     g_h1s[r0 * HS + colj]       = acc[mt][nt][e];
                    if (r0 + 8 < N) g_h1s[(r0 + 8) * HS + colj] = acc[mt][nt][e + 2];
                }
            }
        }
    }
}

// ---------------- aggregate layer 1 (dinv folded here, +b1, leaky_relu) -------
// one warp per node; unrolled x4 neighbor loop for MLP
__global__ __launch_bounds__(256) void agg1_kernel(const float* __restrict__ b1) {
    int warp = (blockIdx.x * 256 + threadIdx.x) >> 5;
    if (warp >= N) return;
    int lane = threadIdx.x & 31;

    const float* hs = g_h1s + (size_t)warp * HS;
    float dvw = g_dinv[warp];
    float s0 = hs[lane] * dvw;
    float s1 = hs[lane + 32] * dvw;
    float s2 = (lane < 3) ? hs[lane + 64] * dvw : 0.f;

    int n = g_cnt[warp];
    const int* rp = g_rows + g_start[warp];
    int k = 0;
    for (; k + 4 <= n; k += 4) {
        int r0 = rp[k], r1 = rp[k + 1], r2 = rp[k + 2], r3 = rp[k + 3];
        float d0 = g_dinv[r0], d1 = g_dinv[r1], d2 = g_dinv[r2], d3 = g_dinv[r3];
        const float* h0 = g_h1s + (size_t)r0 * HS;
        const float* h1 = g_h1s + (size_t)r1 * HS;
        const float* h2 = g_h1s + (size_t)r2 * HS;
        const float* h3 = g_h1s + (size_t)r3 * HS;
        s0 = fmaf(h0[lane], d0, s0);
        s0 = fmaf(h1[lane], d1, s0);
        s0 = fmaf(h2[lane], d2, s0);
        s0 = fmaf(h3[lane], d3, s0);
        s1 = fmaf(h0[lane + 32], d0, s1);
        s1 = fmaf(h1[lane + 32], d1, s1);
        s1 = fmaf(h2[lane + 32], d2, s1);
        s1 = fmaf(h3[lane + 32], d3, s1);
        if (lane < 3) {
            s2 = fmaf(h0[lane + 64], d0, s2);
            s2 = fmaf(h1[lane + 64], d1, s2);
            s2 = fmaf(h2[lane + 64], d2, s2);
            s2 = fmaf(h3[lane + 64], d3, s2);
        }
    }
    for (; k < n; k++) {
        int r = rp[k];
        float dr = g_dinv[r];
        const float* hr = g_h1s + (size_t)r * HS;
        s0 = fmaf(hr[lane], dr, s0);
        s1 = fmaf(hr[lane + 32], dr, s1);
        if (lane < 3) s2 = fmaf(hr[lane + 64], dr, s2);
    }
    float* out = g_a1 + (size_t)warp * H;
    float v;
    v = fmaf(dvw, s0, b1[lane]);      out[lane]      = (v > 0.f) ? v : 0.01f * v;
    v = fmaf(dvw, s1, b1[lane + 32]); out[lane + 32] = (v > 0.f) ? v : 0.01f * v;
    if (lane < 3) {
        v = fmaf(dvw, s2, b1[lane + 64]); out[lane + 64] = (v > 0.f) ? v : 0.01f * v;
    }
}

// ---------------- GEMM2: h2s = (a1 @ W2) * dinv ----------------
__global__ __launch_bounds__(128) void gemm2_kernel(const float* __restrict__ W2) {
    __shared__ float as[128 * H];
    __shared__ float w[H * C];
    int tid = threadIdx.x;
    int base = blockIdx.x * 128;
    int nn = N - base; if (nn > 128) nn = 128;
    int total = nn * H;
    for (int i = tid; i < total; i += 128) as[i] = g_a1[(size_t)base * H + i];
    for (int i = tid; i < H * C; i += 128) w[i] = W2[i];
    __syncthreads();
    if (tid < nn) {
        float acc[C];
        #pragma unroll
        for (int j = 0; j < C; j++) acc[j] = 0.f;
        const float* ar = as + tid * H;
        #pragma unroll 4
        for (int k = 0; k < H; k++) {
            float av = ar[k];
            #pragma unroll
            for (int j = 0; j < C; j++) acc[j] = fmaf(av, w[k * C + j], acc[j]);
        }
        int node = base + tid;
        float dv = g_dinv[node];
        #pragma unroll
        for (int j = 0; j < C; j++) g_h2s[node * C + j] = acc[j] * dv;
    }
}

// ---------------- aggregate layer 2 + b2 + log_softmax ----------------
__global__ __launch_bounds__(256) void agg2_kernel(const float* __restrict__ b2,
                                                   float* __restrict__ out) {
    int warp = (blockIdx.x * 256 + threadIdx.x) >> 5;
    int lane = threadIdx.x & 31;
    int g = lane >> 3, j = lane & 7;
    int n = warp * 4 + g;

    float acc = (j < C) ? g_h2s[n * C + j] : 0.f;
    int sbeg = g_start[n], c = g_cnt[n];
    const int* rp = g_rows + sbeg;
    for (int k = 0; k < c; k++) {
        int r = rp[k];
        if (j < C) acc += g_h2s[r * C + j];
    }
    float logit = (j < C) ? fmaf(g_dinv[n], acc, b2[j]) : -3.0e38f;

    float m = logit;
    #pragma unroll
    for (int o = 4; o > 0; o >>= 1)
        m = fmaxf(m, __shfl_xor_sync(0xffffffffu, m, o, 8));
    float ex = (j < C) ? expf(logit - m) : 0.f;
    float sum = ex;
    #pragma unroll
    for (int o = 4; o > 0; o >>= 1)
        sum += __shfl_xor_sync(0xffffffffu, sum, o, 8);
    if (j < C) out[n * C + j] = logit - m - logf(sum);
}

// ---------------- launch ----------------
extern "C" void kernel_launch(void* const* d_in, const int* in_sizes, int n_in,
                              void* d_out, int out_size) {
    const float* x    = (const float*)d_in[0];
    const int*   ei   = (const int*)d_in[1];
    const float* W1   = (const float*)d_in[2];
    const float* b1   = (const float*)d_in[3];
    const float* W2   = (const float*)d_in[4];
    const float* b2   = (const float*)d_in[5];
    float*       out  = (float*)d_out;

    const int* row = ei;
    const int* col = ei + E;

    int nB = (N + 255) / 256;
    int eB = (E + 255) / 256;
    int sB = (N + 1023) / 1024;

    cudaFuncSetAttribute(gemm1_mma, cudaFuncAttributeMaxDynamicSharedMemorySize,
                         G1_SMEM);

    // gemm1 placed 4th so the profiler (empirically captures launch #4) sees it.
    w1split_kernel<<<(BN * KC16 * 4 + 255) / 256, 256>>>(W1);
    zero_cnt_kernel<<<nB, 256>>>();
    hist_kernel<<<eB, 256>>>(col);
    gemm1_mma<<<(N + 127) / 128, 256, G1_SMEM>>>(x);
    scan1_kernel<<<sB, 1024>>>();
    scan2_kernel<<<1, 128>>>(sB);
    scan3_kernel<<<nB, 256>>>();
    fill_kernel<<<eB, 256>>>(row, col);

    agg1_kernel<<<(N * 32 + 255) / 256, 256>>>(b1);
    gemm2_kernel<<<(N + 127) / 128, 128>>>(W2);
    agg2_kernel<<<(N * 8 + 255) / 256, 256>>>(b2, out);
}